// round 9
// baseline (speedup 1.0000x reference)
#include <cuda_runtime.h>
#include <cstdint>

// out[r][c] = in[2r+1][2c+1], in: 8192x8192 f32, out: 4096x4096 f32.
//
// Final form. DRAM-bound at the measured ~6.0 TB/s mixed read+write HBM
// ceiling: 128 MB read (odd rows; every 32B sector carries needed odd
// columns -> irreducible) + 64 MB write, ~160 MB effective after the L2
// reuse the default cache policy already provides.
//
// Settled by R1-R7 experiments:
//  - default load policy (any streaming/pinning hint on loads regresses)
//  - float4 loads/stores, fully coalesced (512B per warp request)
//  - .cs on stores only (neutral-to-free; single-use full sectors)
//  - 1 output float4 per thread; MLP/row-batching variants all neutral
//
// Each thread: out[row][4v..4v+3] from in[2row+1][8v..8v+7] via two LDG.128.

static constexpr int N_IN  = 8192;
static constexpr int N_OUT = 4096;
static constexpr int VECS_PER_ROW = N_OUT / 4;   // 1024 float4 per output row
static constexpr int IN_ROW_V4    = N_IN / 4;    // 2048 float4 per input row

__global__ void __launch_bounds__(512)
downsample2x_kernel(const float4* __restrict__ in, float4* __restrict__ out) {
    unsigned tid = blockIdx.x * blockDim.x + threadIdx.x;   // 0 .. 4,194,303
    unsigned row = tid >> 10;          // / VECS_PER_ROW
    unsigned vec = tid & 1023;         // % VECS_PER_ROW

    const float4* in_row = in + (size_t)(2u * row + 1u) * IN_ROW_V4;

    float4 a = in_row[2u * vec];
    float4 b = in_row[2u * vec + 1u];

    __stcs(out + (size_t)row * VECS_PER_ROW + vec,
           make_float4(a.y, a.w, b.y, b.w));
}

extern "C" void kernel_launch(void* const* d_in, const int* in_sizes, int n_in,
                              void* d_out, int out_size) {
    const float4* in  = (const float4*)d_in[0];
    float4*       out = (float4*)d_out;

    const int total_threads = N_OUT * VECS_PER_ROW;  // 4,194,304
    const int block = 512;
    const int grid  = total_threads / block;         // 8192

    downsample2x_kernel<<<grid, block>>>(in, out);
}

// round 10
// speedup vs baseline: 1.0077x; 1.0077x over previous
#include <cuda_runtime.h>
#include <cstdint>

// out[r][c] = in[2r+1][2c+1], in: 8192x8192 f32, out: 4096x4096 f32.
//
// FINAL — exact R1 record configuration (32.83 us, 6.0 TB/s).
//
// DRAM-bound at the measured ~6.0 TB/s mixed read+write HBM ceiling:
//   128 MB read (odd rows; every 32B sector carries needed odd columns ->
//   irreducible) + 64 MB write, ~160 MB effective after default-policy L2
//   reuse across graph replays.
//
// Exhaustively settled R1-R9:
//   rows/thread {1,2,4} x width {128b,256b} x load {default,cs,evict_last}
//   x store {default,cs} x block {256,512}: all 32.8-34.6 us; this config
//   is the empirical optimum. Any load-side cache hint regresses; block=512
//   regresses; everything else is noise around the roofline.

static constexpr int N_IN  = 8192;
static constexpr int N_OUT = 4096;
static constexpr int VECS_PER_ROW = N_OUT / 4;   // 1024 float4 per output row
static constexpr int IN_ROW_V4    = N_IN / 4;    // 2048 float4 per input row

__global__ void downsample2x_kernel(const float4* __restrict__ in,
                                    float4* __restrict__ out) {
    unsigned tid = blockIdx.x * blockDim.x + threadIdx.x;   // 0 .. 4,194,303
    unsigned row = tid >> 10;          // / VECS_PER_ROW
    unsigned vec = tid & 1023;         // % VECS_PER_ROW

    const float4* in_row = in + (size_t)(2u * row + 1u) * IN_ROW_V4;

    float4 a = in_row[2u * vec];
    float4 b = in_row[2u * vec + 1u];

    float4 o;
    o.x = a.y;
    o.y = a.w;
    o.z = b.y;
    o.w = b.w;

    out[(size_t)row * VECS_PER_ROW + vec] = o;
}

extern "C" void kernel_launch(void* const* d_in, const int* in_sizes, int n_in,
                              void* d_out, int out_size) {
    const float4* in  = (const float4*)d_in[0];
    float4*       out = (float4*)d_out;

    const int total_threads = N_OUT * VECS_PER_ROW;  // 4,194,304
    const int block = 256;
    const int grid  = total_threads / block;         // 16384

    downsample2x_kernel<<<grid, block>>>(in, out);
}

// round 11
// speedup vs baseline: 1.0727x; 1.0645x over previous
#include <cuda_runtime.h>
#include <cstdint>

// out[r][c] = in[2r+1][2c+1], in: 8192x8192 f32, out: 4096x4096 f32.
//
// DRAM-bound at the measured ~6.1 TB/s mixed read+write HBM ceiling
// (77% of spec; read/write turnaround bound). Traffic floor: 128 MB read
// (odd rows; every 32B sector carries needed odd columns) + 64 MB write.
//
// Design space settled R1-R10: default load+store policy is optimal (all
// cache hints neutral or regressive; background writeback defeats
// output-residency schemes); float4 width; block=256. This round fills the
// last gap: 2 output rows per thread (MLP_p1=4), between the two measured
// optima (1 row: best harness 32.83; 4 rows: best device 26.56).

static constexpr int N_IN  = 8192;
static constexpr int N_OUT = 4096;
static constexpr int VECS_PER_ROW = N_OUT / 4;   // 1024 float4 per output row
static constexpr int IN_ROW_V4    = N_IN / 4;    // 2048 float4 per input row
static constexpr int ROWS_PER_THREAD = 2;

__global__ void downsample2x_kernel(const float4* __restrict__ in,
                                    float4* __restrict__ out) {
    unsigned tid = blockIdx.x * blockDim.x + threadIdx.x;  // 0 .. 2,097,151
    unsigned vec = tid & (VECS_PER_ROW - 1);               // 0..1023
    unsigned rg  = tid >> 10;                              // row group 0..2047

    // Output rows 2rg, 2rg+1  <-  input rows 4rg+1, 4rg+3.
    const float4* p = in + (size_t)(4u * rg + 1u) * IN_ROW_V4 + 2u * vec;

    // Front-batched default-policy loads (4 independent LDG.128).
    float4 a0 = p[0];
    float4 b0 = p[1];
    float4 a1 = p[2 * IN_ROW_V4];
    float4 b1 = p[2 * IN_ROW_V4 + 1];

    float4* q = out + (size_t)(2u * rg) * VECS_PER_ROW + vec;

    q[0]            = make_float4(a0.y, a0.w, b0.y, b0.w);
    q[VECS_PER_ROW] = make_float4(a1.y, a1.w, b1.y, b1.w);
}

extern "C" void kernel_launch(void* const* d_in, const int* in_sizes, int n_in,
                              void* d_out, int out_size) {
    const float4* in  = (const float4*)d_in[0];
    float4*       out = (float4*)d_out;

    const int total_threads = (N_OUT / ROWS_PER_THREAD) * VECS_PER_ROW; // 2,097,152
    const int block = 256;
    const int grid  = total_threads / block;                            // 8192

    downsample2x_kernel<<<grid, block>>>(in, out);
}